// round 2
// baseline (speedup 1.0000x reference)
#include <cuda_runtime.h>
#include <math.h>

#define Bsz  256
#define Tlen 512
#define IN   512
#define HID  1024
#define OUTD 512
#define G3   (3 * HID)

// Scratch: precomputed input projections [T][B][3H] (~1.6 GB) and ping-pong h.
__device__ float g_xpre[(size_t)Tlen * Bsz * G3];
__device__ float g_h[2][Bsz * HID];

// ---------------------------------------------------------------------------
__global__ void zero_h_kernel() {
    int i = blockIdx.x * blockDim.x + threadIdx.x;
    if (i < Bsz * HID) g_h[0][i] = 0.0f;
}

// ---------------------------------------------------------------------------
// X projection: out[t][b][g*H+j] = sum_i x[b][t][i] * Wx_g[j][i] + bx_g[j]
// M = B*T (m = b*T + t, matches x layout), N = 3072, K = 512.
// Tile 128x128x8, 256 threads, 8x8 microtile.
__global__ void gemm_x_kernel(const float* __restrict__ x,
                              const float* __restrict__ Wxr, const float* __restrict__ bxr,
                              const float* __restrict__ Wxc, const float* __restrict__ bxc,
                              const float* __restrict__ Wxz, const float* __restrict__ bxz) {
    const int BM = 128, BN = 128, BK = 8;
    __shared__ float As[BK][BM];
    __shared__ float Bs[BK][BN];

    const int n0 = blockIdx.x * BN;
    const int m0 = blockIdx.y * BM;
    const int g  = n0 >> 10;                    // 1024 % 128 == 0: whole block one gate
    const float* __restrict__ W    = (g == 0) ? Wxr : ((g == 1) ? Wxc : Wxz);
    const float* __restrict__ bias = (g == 0) ? bxr : ((g == 1) ? bxc : bxz);
    const int j0 = n0 - (g << 10);

    const int tid = threadIdx.x;
    const int a_row = tid >> 1;
    const int a_col = (tid & 1) * 4;

    const int tx = tid & 15;    // n micro index
    const int ty = tid >> 4;    // m micro index

    float acc[8][8];
#pragma unroll
    for (int i = 0; i < 8; i++)
#pragma unroll
        for (int j = 0; j < 8; j++) acc[i][j] = 0.0f;

    for (int k0 = 0; k0 < IN; k0 += BK) {
        float4 av = *(const float4*)(x + (size_t)(m0 + a_row) * IN + k0 + a_col);
        As[a_col + 0][a_row] = av.x;
        As[a_col + 1][a_row] = av.y;
        As[a_col + 2][a_row] = av.z;
        As[a_col + 3][a_row] = av.w;
        float4 bv = *(const float4*)(W + (size_t)(j0 + a_row) * IN + k0 + a_col);
        Bs[a_col + 0][a_row] = bv.x;
        Bs[a_col + 1][a_row] = bv.y;
        Bs[a_col + 2][a_row] = bv.z;
        Bs[a_col + 3][a_row] = bv.w;
        __syncthreads();

#pragma unroll
        for (int k = 0; k < BK; k++) {
            float4 a0 = *(const float4*)&As[k][ty * 8];
            float4 a1 = *(const float4*)&As[k][ty * 8 + 4];
            float4 b0 = *(const float4*)&Bs[k][tx * 8];
            float4 b1 = *(const float4*)&Bs[k][tx * 8 + 4];
            float a[8] = {a0.x, a0.y, a0.z, a0.w, a1.x, a1.y, a1.z, a1.w};
            float b[8] = {b0.x, b0.y, b0.z, b0.w, b1.x, b1.y, b1.z, b1.w};
#pragma unroll
            for (int i = 0; i < 8; i++)
#pragma unroll
                for (int j = 0; j < 8; j++)
                    acc[i][j] = fmaf(a[i], b[j], acc[i][j]);
        }
        __syncthreads();
    }

#pragma unroll
    for (int i = 0; i < 8; i++) {
        const int m = m0 + ty * 8 + i;
        const int b = m >> 9;          // / Tlen
        const int t = m & (Tlen - 1);
        const size_t base = ((size_t)t * Bsz + b) * G3 + n0;
#pragma unroll
        for (int j = 0; j < 8; j++) {
            const int nl = tx * 8 + j;
            g_xpre[base + nl] = acc[i][j] + bias[j0 + nl];
        }
    }
}

// ---------------------------------------------------------------------------
// One GRU timestep, fully fused: three gate GEMMs (shared h tile) + GRU update.
// Tiles: BM=32 (batch), BN=64 (hidden cols), BK=32. 128 threads, 4x4 micro x3.
// Grid: (16, 8) = 128 CTAs.
__global__ void gru_step_kernel(const float* __restrict__ Whr, const float* __restrict__ bhr,
                                const float* __restrict__ Whc, const float* __restrict__ bhc,
                                const float* __restrict__ Whz, const float* __restrict__ bhz,
                                int t) {
    const int BM = 32, BN = 64, BK = 32;
    __shared__ float Hs[BK][BM];
    __shared__ float Ws[3][BK][BN];

    const int par = t & 1;
    const float* __restrict__ hprev = g_h[par];
    float* __restrict__ hnext = g_h[par ^ 1];

    const int n0 = blockIdx.x * BN;
    const int m0 = blockIdx.y * BM;
    const int tid = threadIdx.x;   // 128

    // H load mapping: 32 rows x 4 k-quads of 8
    const int hr = tid >> 2;
    const int hq = (tid & 3) * 8;
    // W load mapping: 64 rows x 2 k-halves of 16
    const int wr = tid >> 1;
    const int wq = (tid & 1) * 16;

    const int tm = tid >> 4;   // 0..7  -> 4 batch rows
    const int tn = tid & 15;   // 0..15 -> 4 cols

    float ar[4][4], ac[4][4], az[4][4];
#pragma unroll
    for (int i = 0; i < 4; i++)
#pragma unroll
        for (int j = 0; j < 4; j++) { ar[i][j] = 0.f; ac[i][j] = 0.f; az[i][j] = 0.f; }

    const float* __restrict__ Wg[3] = {Whr, Whc, Whz};

    for (int k0 = 0; k0 < HID; k0 += BK) {
        {
            const float* hp = hprev + (size_t)(m0 + hr) * HID + k0 + hq;
            float4 h0 = *(const float4*)hp;
            float4 h1 = *(const float4*)(hp + 4);
            Hs[hq + 0][hr] = h0.x; Hs[hq + 1][hr] = h0.y;
            Hs[hq + 2][hr] = h0.z; Hs[hq + 3][hr] = h0.w;
            Hs[hq + 4][hr] = h1.x; Hs[hq + 5][hr] = h1.y;
            Hs[hq + 6][hr] = h1.z; Hs[hq + 7][hr] = h1.w;
        }
#pragma unroll
        for (int g = 0; g < 3; g++) {
            const float* wp = Wg[g] + (size_t)(n0 + wr) * HID + k0 + wq;
#pragma unroll
            for (int u = 0; u < 4; u++) {
                float4 wv = *(const float4*)(wp + u * 4);
                Ws[g][wq + u * 4 + 0][wr] = wv.x;
                Ws[g][wq + u * 4 + 1][wr] = wv.y;
                Ws[g][wq + u * 4 + 2][wr] = wv.z;
                Ws[g][wq + u * 4 + 3][wr] = wv.w;
            }
        }
        __syncthreads();

#pragma unroll
        for (int k = 0; k < BK; k++) {
            float4 hv = *(const float4*)&Hs[k][tm * 4];
            float4 wrv = *(const float4*)&Ws[0][k][tn * 4];
            float4 wcv = *(const float4*)&Ws[1][k][tn * 4];
            float4 wzv = *(const float4*)&Ws[2][k][tn * 4];
            float h4[4] = {hv.x, hv.y, hv.z, hv.w};
            float r4[4] = {wrv.x, wrv.y, wrv.z, wrv.w};
            float c4[4] = {wcv.x, wcv.y, wcv.z, wcv.w};
            float z4[4] = {wzv.x, wzv.y, wzv.z, wzv.w};
#pragma unroll
            for (int i = 0; i < 4; i++)
#pragma unroll
                for (int j = 0; j < 4; j++) {
                    ar[i][j] = fmaf(h4[i], r4[j], ar[i][j]);
                    ac[i][j] = fmaf(h4[i], c4[j], ac[i][j]);
                    az[i][j] = fmaf(h4[i], z4[j], az[i][j]);
                }
        }
        __syncthreads();
    }

    // Fused GRU elementwise update
#pragma unroll
    for (int i = 0; i < 4; i++) {
        const int b = m0 + tm * 4 + i;
        const size_t xbase = ((size_t)t * Bsz + b) * G3;
#pragma unroll
        for (int j = 0; j < 4; j++) {
            const int col = n0 + tn * 4 + j;
            const float xr = g_xpre[xbase + col];
            const float xc = g_xpre[xbase + HID + col];
            const float xz = g_xpre[xbase + 2 * HID + col];
            const float hold = hprev[(size_t)b * HID + col];
            const float r = 1.0f / (1.0f + expf(-(xr + ar[i][j] + bhr[col])));
            const float c = tanhf(xc + r * (ac[i][j] + bhc[col]));
            const float z = 1.0f / (1.0f + expf(-(xz + az[i][j] + bhz[col])));
            hnext[(size_t)b * HID + col] = (1.0f - z) * hold + z * c;
        }
    }
}

// ---------------------------------------------------------------------------
// out[b][o] = sum_k h_final[b][k] * Wo[o][k] + bo[o]   (h_final = g_h[0])
// BM=32, BN=64, BK=32, 128 threads, 4x4 micro. Grid (8, 8).
__global__ void gemm_out_kernel(const float* __restrict__ Wo, const float* __restrict__ bo,
                                float* __restrict__ out) {
    const int BM = 32, BN = 64, BK = 32;
    __shared__ float Hs[BK][BM];
    __shared__ float Ws[BK][BN];

    const float* __restrict__ h = g_h[0];
    const int n0 = blockIdx.x * BN;
    const int m0 = blockIdx.y * BM;
    const int tid = threadIdx.x;

    const int hr = tid >> 2;
    const int hq = (tid & 3) * 8;
    const int wr = tid >> 1;
    const int wq = (tid & 1) * 16;
    const int tm = tid >> 4;
    const int tn = tid & 15;

    float acc[4][4];
#pragma unroll
    for (int i = 0; i < 4; i++)
#pragma unroll
        for (int j = 0; j < 4; j++) acc[i][j] = 0.f;

    for (int k0 = 0; k0 < HID; k0 += BK) {
        {
            const float* hp = h + (size_t)(m0 + hr) * HID + k0 + hq;
            float4 h0 = *(const float4*)hp;
            float4 h1 = *(const float4*)(hp + 4);
            Hs[hq + 0][hr] = h0.x; Hs[hq + 1][hr] = h0.y;
            Hs[hq + 2][hr] = h0.z; Hs[hq + 3][hr] = h0.w;
            Hs[hq + 4][hr] = h1.x; Hs[hq + 5][hr] = h1.y;
            Hs[hq + 6][hr] = h1.z; Hs[hq + 7][hr] = h1.w;
        }
        {
            const float* wp = Wo + (size_t)(n0 + wr) * HID + k0 + wq;
#pragma unroll
            for (int u = 0; u < 4; u++) {
                float4 wv = *(const float4*)(wp + u * 4);
                Ws[wq + u * 4 + 0][wr] = wv.x;
                Ws[wq + u * 4 + 1][wr] = wv.y;
                Ws[wq + u * 4 + 2][wr] = wv.z;
                Ws[wq + u * 4 + 3][wr] = wv.w;
            }
        }
        __syncthreads();

#pragma unroll
        for (int k = 0; k < BK; k++) {
            float4 hv = *(const float4*)&Hs[k][tm * 4];
            float4 wv = *(const float4*)&Ws[k][tn * 4];
            float h4[4] = {hv.x, hv.y, hv.z, hv.w};
            float w4[4] = {wv.x, wv.y, wv.z, wv.w};
#pragma unroll
            for (int i = 0; i < 4; i++)
#pragma unroll
                for (int j = 0; j < 4; j++)
                    acc[i][j] = fmaf(h4[i], w4[j], acc[i][j]);
        }
        __syncthreads();
    }

#pragma unroll
    for (int i = 0; i < 4; i++) {
        const int b = m0 + tm * 4 + i;
#pragma unroll
        for (int j = 0; j < 4; j++) {
            const int o = n0 + tn * 4 + j;
            out[(size_t)b * OUTD + o] = acc[i][j] + bo[o];
        }
    }
}

// ---------------------------------------------------------------------------
extern "C" void kernel_launch(void* const* d_in, const int* in_sizes, int n_in,
                              void* d_out, int out_size) {
    const float* x   = (const float*)d_in[0];
    const float* Wxr = (const float*)d_in[1];
    const float* bxr = (const float*)d_in[2];
    const float* Whr = (const float*)d_in[3];
    const float* bhr = (const float*)d_in[4];
    const float* Wxc = (const float*)d_in[5];
    const float* bxc = (const float*)d_in[6];
    const float* Whc = (const float*)d_in[7];
    const float* bhc = (const float*)d_in[8];
    const float* Wxz = (const float*)d_in[9];
    const float* bxz = (const float*)d_in[10];
    const float* Whz = (const float*)d_in[11];
    const float* bhz = (const float*)d_in[12];
    const float* Wo  = (const float*)d_in[13];
    const float* bo  = (const float*)d_in[14];
    float* out = (float*)d_out;

    zero_h_kernel<<<(Bsz * HID + 255) / 256, 256>>>();
    gemm_x_kernel<<<dim3(G3 / 128, (Bsz * Tlen) / 128), 256>>>(x, Wxr, bxr, Wxc, bxc, Wxz, bxz);
    for (int t = 0; t < Tlen; t++)
        gru_step_kernel<<<dim3(HID / 64, Bsz / 32), 128>>>(Whr, bhr, Whc, bhc, Whz, bhz, t);
    gemm_out_kernel<<<dim3(OUTD / 64, Bsz / 32), 128>>>(Wo, bo, out);
}